// round 6
// baseline (speedup 1.0000x reference)
#include <cuda_runtime.h>
#include <cstring>
#include <cfloat>
#include <cmath>

// Problem shape: activations [B=64, C=256, L=512] float32.
#define C_DIM 256
#define B_DIM 64
#define L_DIM 512
#define N_PER_C (B_DIM * L_DIM)               // 32768 per channel
#define F4_PER_ROW (L_DIM / 4)                // 128
#define F4_PER_C (N_PER_C / 4)                // 8192
#define TOTAL_F4 (B_DIM * C_DIM * L_DIM / 4)  // 2097152

#define NB 1024                                // bucket count
#define BSCALE 819.2f                          // NB / 1.25

// Per-channel affine coefficients: y = x * g_scale[c] + g_shift[c]
__device__ float g_scale[C_DIM];
__device__ float g_shift[C_DIM];

// Partial sums: 4 partials per channel, fixed combine order (deterministic).
__device__ double g_ps[C_DIM * 4];
__device__ double g_pq[C_DIM * 4];

// Bucket table staged to global by finalize kernel, loaded to smem per block.
__device__ float4 g_tab[NB];

struct BucketTab { float4 b[NB]; };   // 16 KB by-value kernel param
struct LifTab    { float e[64]; float v[64]; };

// ---------------------------------------------------------------------------
// Kernel 1: partial per-channel sums. 1024 blocks: c = b>>2, quarter = b&3.
// ---------------------------------------------------------------------------
__global__ void __launch_bounds__(256) stats_partial_kernel(
    const float* __restrict__ act)
{
    const int b = blockIdx.x;
    const int c = b >> 2;
    const int q = b & 3;
    const int tid = threadIdx.x;
    const float4* a4 = (const float4*)act;

    float s0 = 0.f, s1 = 0.f, s2 = 0.f, s3 = 0.f;
    float q0 = 0.f, q1 = 0.f, q2 = 0.f, q3 = 0.f;

    #pragma unroll
    for (int k = 0; k < 8; ++k) {
        const int j = q * 2048 + k * 256 + tid;     // quarter of F4_PER_C
        const int bb  = j >> 7;
        const int pos = j & 127;
        float4 v = a4[bb * (C_DIM * F4_PER_ROW) + c * F4_PER_ROW + pos];
        s0 += v.x; s1 += v.y; s2 += v.z; s3 += v.w;
        q0 = fmaf(v.x, v.x, q0);
        q1 = fmaf(v.y, v.y, q1);
        q2 = fmaf(v.z, v.z, q2);
        q3 = fmaf(v.w, v.w, q3);
    }

    double s = (double)s0 + (double)s1 + (double)s2 + (double)s3;
    double qq = (double)q0 + (double)q1 + (double)q2 + (double)q3;

    __shared__ double sh_s[256];
    __shared__ double sh_q[256];
    sh_s[tid] = s;
    sh_q[tid] = qq;
    __syncthreads();

    #pragma unroll
    for (int off = 128; off > 0; off >>= 1) {
        if (tid < off) {
            sh_s[tid] += sh_s[tid + off];
            sh_q[tid] += sh_q[tid + off];
        }
        __syncthreads();
    }

    if (tid == 0) {
        g_ps[b] = sh_s[0];
        g_pq[b] = sh_q[0];
    }
}

// ---------------------------------------------------------------------------
// Kernel 2: finalize coefficients (1 thread per channel) + stage bucket table.
// ---------------------------------------------------------------------------
__global__ void __launch_bounds__(256) finalize_kernel(
    const float* __restrict__ w,
    const float* __restrict__ bias,
    const BucketTab tab)
{
    const int tid = threadIdx.x;

    // Fixed-order combine of the 4 partials -> deterministic.
    {
        const int c = tid;
        double s = ((g_ps[4*c] + g_ps[4*c+1]) + g_ps[4*c+2]) + g_ps[4*c+3];
        double q = ((g_pq[4*c] + g_pq[4*c+1]) + g_pq[4*c+2]) + g_pq[4*c+3];
        const double inv_n = 1.0 / (double)N_PER_C;
        double mean = s * inv_n;
        double var  = q * inv_n - mean * mean;
        double scale = (double)w[c] * rsqrt(var + 1e-5);
        g_scale[c] = (float)scale;
        g_shift[c] = (float)((double)bias[c] - mean * scale);
    }

    for (int i = tid; i < NB; i += 256)
        g_tab[i] = tab.b[i];
}

// ---------------------------------------------------------------------------
// Kernel 3a (fast path): direct-mapped bucket lookup.
// bucket = (e1, e2, v0, packed{d1,d2 as bf16 hi/lo})
// f(a) = v0 + (a>e1)*d1 + (a>e2)*d2 ; result sign = sign(x).
// ---------------------------------------------------------------------------
__global__ void __launch_bounds__(256) lif_bucket_kernel(
    const float* __restrict__ act,
    float* __restrict__ out)
{
    __shared__ float4 sb[NB];
    for (int i = threadIdx.x; i < NB; i += 256)
        sb[i] = g_tab[i];                 // coalesced LDG.128
    __syncthreads();

    const int i = blockIdx.x * 256 + threadIdx.x;   // float4 index
    const int c = (i >> 7) & (C_DIM - 1);

    const float sc = g_scale[c];
    const float sh = g_shift[c];

    float4 v = ((const float4*)act)[i];
    float xs[4] = { fmaf(v.x, sc, sh), fmaf(v.y, sc, sh),
                    fmaf(v.z, sc, sh), fmaf(v.w, sc, sh) };
    float r[4];

    #pragma unroll
    for (int k = 0; k < 4; ++k) {
        const float a = fabsf(xs[k]);
        int idx = (int)(a * BSCALE);
        idx = min(idx, NB - 1);
        const float4 bk = sb[idx];
        const int wb = __float_as_int(bk.w);
        const float d1 = __int_as_float(wb << 16);
        const float d2 = __int_as_float(wb & 0xFFFF0000);
        float val = bk.z;
        val += (a > bk.x) ? d1 : 0.0f;
        val += (a > bk.y) ? d2 : 0.0f;
        r[k] = __int_as_float(__float_as_int(val) |
                              (__float_as_int(xs[k]) & 0x80000000));
    }

    ((float4*)out)[i] = make_float4(r[0], r[1], r[2], r[3]);
}

// ---------------------------------------------------------------------------
// Kernel 3b (fallback, R5-verified): 64-entry binary-search LUT.
// ---------------------------------------------------------------------------
__global__ void __launch_bounds__(256) lif_lut_kernel(
    const float* __restrict__ act,
    float* __restrict__ out,
    const LifTab tab)
{
    __shared__ float se[64];
    __shared__ float sv[64];
    if (threadIdx.x < 64) {
        se[threadIdx.x] = tab.e[threadIdx.x];
        sv[threadIdx.x] = tab.v[threadIdx.x];
    }
    __syncthreads();

    const int i = blockIdx.x * 256 + threadIdx.x;
    const int c = (i >> 7) & (C_DIM - 1);

    const float sc = g_scale[c];
    const float sh = g_shift[c];

    float4 v = ((const float4*)act)[i];
    float xs[4] = { fmaf(v.x, sc, sh), fmaf(v.y, sc, sh),
                    fmaf(v.z, sc, sh), fmaf(v.w, sc, sh) };
    float r[4];

    #pragma unroll
    for (int k = 0; k < 4; ++k) {
        const float a = fabsf(xs[k]);
        int pos = 0;
        #pragma unroll
        for (int s = 32; s > 0; s >>= 1)
            if (se[pos + s - 1] < a) pos += s;
        const float val = sv[pos];
        r[k] = __int_as_float(__float_as_int(val) |
                              (__float_as_int(xs[k]) & 0x80000000));
    }

    ((float4*)out)[i] = make_float4(r[0], r[1], r[2], r[3]);
}

// ---------------------------------------------------------------------------
// Kernel 3c (last-resort fallback, R2-verified): direct 16-step scan.
// ---------------------------------------------------------------------------
__device__ __forceinline__ float lif16(float x)
{
    float mem = x;
    float sgn = __int_as_float((__float_as_int(mem) & 0x80000000) | 0x3f800000);
    float spk = (fabsf(mem) > 1.0f) ? sgn : 0.0f;
    float sum = spk;

    #pragma unroll
    for (int t = 1; t < 16; ++t) {
        mem = fmaf(0.9f, mem, x - spk);
        sgn = __int_as_float((__float_as_int(mem) & 0x80000000) | 0x3f800000);
        spk = (fabsf(mem) > 1.0f) ? sgn : 0.0f;
        sum += spk;
    }
    return sum * 0.0625f;
}

__global__ void __launch_bounds__(256) lif_kernel(
    const float* __restrict__ act,
    float* __restrict__ out)
{
    const int i = blockIdx.x * 256 + threadIdx.x;
    const int c = (i >> 7) & (C_DIM - 1);
    const float sc = g_scale[c];
    const float sh = g_shift[c];
    float4 v = ((const float4*)act)[i];
    float4 r;
    r.x = lif16(fmaf(v.x, sc, sh));
    r.y = lif16(fmaf(v.y, sc, sh));
    r.z = lif16(fmaf(v.z, sc, sh));
    r.w = lif16(fmaf(v.w, sc, sh));
    ((float4*)out)[i] = r;
}

// ===========================================================================
// Host-side machinery: bit-exact function replica, edge enumeration, tables.
// ===========================================================================
static float host_lif16(float x)
{
    float mem = x;
    float spk = (fabsf(mem) > 1.0f) ? copysignf(1.0f, mem) : 0.0f;
    float sum = spk;
    for (int t = 1; t < 16; ++t) {
        mem = fmaf(0.9f, mem, x - spk);
        spk = (fabsf(mem) > 1.0f) ? copysignf(1.0f, mem) : 0.0f;
        sum += spk;
    }
    return sum * 0.0625f;
}

static inline unsigned f2u(float f) { unsigned u; std::memcpy(&u, &f, 4); return u; }
static inline float u2f(unsigned u) { float f; std::memcpy(&f, &u, 4); return f; }

static float host_bisect_edge(float lo, float hi, float vlo)
{
    for (int it = 0; it < 64; ++it) {
        unsigned a = f2u(lo), b = f2u(hi);
        if (b - a <= 1u) break;
        float m = u2f(a + (b - a) / 2u);
        if (host_lif16(m) == vlo) lo = m; else hi = m;
    }
    return lo;
}

// Enumerate edges/vals of the piecewise-constant f(|x|). Returns K (#edges)
// or -1 on overflow. vals has K+1 entries.
static int host_find_edges(float* edges, float* vals, int maxK)
{
    int K = 0;
    float cur = host_lif16(0.0f);
    float px = 0.0f;
    vals[0] = cur;
    bool overflow = false;

    auto feed = [&](float x) {
        float fv = host_lif16(x);
        if (fv != cur) {
            if (K < maxK) {
                edges[K] = host_bisect_edge(px, x, cur);
                ++K;
                vals[K] = fv;
            } else overflow = true;
            cur = fv;
        }
        px = x;
    };

    const int N1 = 1 << 20;
    for (int j = 1; j <= N1; ++j)
        feed(1.25f * ((float)j * (1.0f / (float)N1)));
    for (int j = 1; j <= 15104; ++j)
        feed(1.25f + (float)j * 0.0009765625f);

    return overflow ? -1 : K;
}

static inline int host_bidx(float a)
{
    int idx = (int)(a * BSCALE);
    return idx > NB - 1 ? NB - 1 : idx;
}

static float host_bucket_eval(const BucketTab& bt, float a)
{
    const float4& b = bt.b[host_bidx(a)];
    unsigned wb = f2u(b.w);
    float d1 = u2f(wb << 16);
    float d2 = u2f(wb & 0xFFFF0000u);
    float val = b.z;
    val += (a > b.x) ? d1 : 0.0f;
    val += (a > b.y) ? d2 : 0.0f;
    return val;
}

// Build + validate bucket table. Returns true iff bit-exact vs host_lif16.
static bool host_build_buckets(BucketTab& bt,
                               const float* edges, const float* vals, int K)
{
    int i = 0;
    for (int j = 0; j < NB; ++j) {
        if (i < K && host_bidx(edges[i]) < j) return false;  // ordering broke
        int i0 = i, cnt = 0;
        while (i < K && host_bidx(edges[i]) == j) { ++cnt; ++i; }
        if (cnt > 2) return false;

        float e1 = FLT_MAX, e2 = FLT_MAX, d1 = 0.f, d2 = 0.f;
        float v0 = vals[i0];
        if (cnt >= 1) { e1 = edges[i0];     d1 = vals[i0+1] - vals[i0]; }
        if (cnt == 2) { e2 = edges[i0 + 1]; d2 = vals[i0+2] - vals[i0+1]; }

        unsigned u1 = f2u(d1), u2 = f2u(d2);
        if ((u1 & 0xFFFFu) || (u2 & 0xFFFFu)) return false;  // not bf16-exact
        float4 b;
        b.x = e1; b.y = e2; b.z = v0;
        b.w = u2f((u2 & 0xFFFF0000u) | (u1 >> 16));
        bt.b[j] = b;
    }
    if (i != K) return false;

    // ---- Validation: composed lookup must equal host_lif16 everywhere probed.
    auto chk = [&](float a) -> bool {
        float ref = host_lif16(a);
        return ref >= 0.0f && host_bucket_eval(bt, a) == ref;
    };
    for (int k = 0; k < K; ++k) {
        float e = edges[k];
        if (!chk(e)) return false;
        if (!chk(u2f(f2u(e) + 1u))) return false;
        if (f2u(e) > 0 && !chk(u2f(f2u(e) - 1u))) return false;
    }
    for (int j = 1; j < NB; ++j) {               // bucket boundaries +/- 1 ulp
        float bnd = (float)j * (1.25f / (float)NB);
        if (!chk(bnd)) return false;
        if (!chk(u2f(f2u(bnd) + 1u))) return false;
        if (!chk(u2f(f2u(bnd) - 1u))) return false;
    }
    const int N1 = 1 << 20;                      // dense grid
    for (int j = 0; j <= N1; ++j)
        if (!chk(1.25f * ((float)j * (1.0f / (float)N1)))) return false;
    for (int j = 1; j <= 2048; ++j)              // tail
        if (!chk(1.25f + (float)j * 0.0073242187f)) return false;
    return true;
}

static float host_lut_eval(const LifTab& tab, float a)
{
    int pos = 0;
    for (int s = 32; s > 0; s >>= 1)
        if (tab.e[pos + s - 1] < a) pos += s;
    return tab.v[pos];
}

// Build + validate the 64-entry binary-search table (R5 path).
static bool host_build_lut(LifTab& tab,
                           const float* edges, const float* vals, int K)
{
    if (K > 63) return false;
    for (int i2 = K; i2 < 64; ++i2) tab.e[i2] = FLT_MAX;
    for (int i2 = 0; i2 < K; ++i2)  tab.e[i2] = edges[i2];
    for (int i2 = 0; i2 <= K; ++i2) tab.v[i2] = vals[i2];
    for (int i2 = K + 1; i2 < 64; ++i2) tab.v[i2] = vals[K];

    for (int i2 = 0; i2 < K; ++i2) {
        float e = tab.e[i2];
        float eu = u2f(f2u(e) + 1u);
        if (host_lut_eval(tab, e)  != host_lif16(e))  return false;
        if (host_lut_eval(tab, eu) != host_lif16(eu)) return false;
    }
    for (int j = 0; j <= 4096; ++j) {
        float x = 1.25f * ((float)j / 4096.0f);
        if (host_lut_eval(tab, x) != host_lif16(x)) return false;
    }
    return true;
}

// ---------------------------------------------------------------------------
// Launch. Inputs (metadata order): activations, bn_weight, bn_bias.
// ---------------------------------------------------------------------------
extern "C" void kernel_launch(void* const* d_in, const int* in_sizes, int n_in,
                              void* d_out, int out_size)
{
    const float* act  = (const float*)d_in[0];
    const float* w    = (const float*)d_in[1];
    const float* bias = (const float*)d_in[2];
    float* out = (float*)d_out;

    static float edges[96], vals[97];
    int K = host_find_edges(edges, vals, 90);

    static BucketTab btab;                      // 16 KB; static: keep off stack
    bool bucket_ok = (K >= 0) && host_build_buckets(btab, edges, vals, K);
    LifTab ltab;
    bool lut_ok = (K >= 0) && host_build_lut(ltab, edges, vals, K);

    if (!bucket_ok)
        std::memset(&btab, 0, sizeof(btab));    // unused but defined

    stats_partial_kernel<<<C_DIM * 4, 256>>>(act);
    finalize_kernel<<<1, 256>>>(w, bias, btab);

    if (bucket_ok)
        lif_bucket_kernel<<<TOTAL_F4 / 256, 256>>>(act, out);
    else if (lut_ok)
        lif_lut_kernel<<<TOTAL_F4 / 256, 256>>>(act, out, ltab);
    else
        lif_kernel<<<TOTAL_F4 / 256, 256>>>(act, out);
}

// round 9
// speedup vs baseline: 1.5000x; 1.5000x over previous
#include <cuda_runtime.h>
#include <cstring>
#include <cfloat>
#include <cmath>

// Problem shape: activations [B=64, C=256, L=512] float32.
#define C_DIM 256
#define B_DIM 64
#define L_DIM 512
#define N_PER_C (B_DIM * L_DIM)               // 32768 per channel
#define F4_PER_ROW (L_DIM / 4)                // 128
#define F4_PER_C (N_PER_C / 4)                // 8192
#define TOTAL_F4 (B_DIM * C_DIM * L_DIM / 4)  // 2097152

#define NB 2048                                // bucket count
#define BSCALE 1638.4f                         // NB / 1.25

#define LIF_BLOCKS 1024
#define LIF_CHUNKS 8                           // 1024*256*8 == TOTAL_F4

// Per-channel affine coefficients: y = x * g_scale[c] + g_shift[c]
__device__ float g_scale[C_DIM];
__device__ float g_shift[C_DIM];

// Bucket table in global, staged to smem per block.
__device__ float2 g_tab[NB];

struct BucketTab { float2 b[NB]; };   // 16 KB by-value kernel param
struct LifTab    { float e[64]; float v[64]; };

// ---------------------------------------------------------------------------
// Kernel 1: per-channel mean/var -> scale & shift. (R2-verified, 4.8 us)
// ---------------------------------------------------------------------------
__global__ void __launch_bounds__(256) bn_stats_kernel(
    const float* __restrict__ act,
    const float* __restrict__ w,
    const float* __restrict__ bias)
{
    const int c = blockIdx.x;
    const int tid = threadIdx.x;
    const float4* a4 = (const float4*)act;

    float s0 = 0.f, s1 = 0.f, s2 = 0.f, s3 = 0.f;
    float q0 = 0.f, q1 = 0.f, q2 = 0.f, q3 = 0.f;

    #pragma unroll 4
    for (int j = tid; j < F4_PER_C; j += 256) {
        const int bb  = j >> 7;
        const int pos = j & 127;
        float4 v = a4[bb * (C_DIM * F4_PER_ROW) + c * F4_PER_ROW + pos];
        s0 += v.x; s1 += v.y; s2 += v.z; s3 += v.w;
        q0 = fmaf(v.x, v.x, q0);
        q1 = fmaf(v.y, v.y, q1);
        q2 = fmaf(v.z, v.z, q2);
        q3 = fmaf(v.w, v.w, q3);
    }

    double s = (double)s0 + (double)s1 + (double)s2 + (double)s3;
    double q = (double)q0 + (double)q1 + (double)q2 + (double)q3;

    __shared__ double sh_s[256];
    __shared__ double sh_q[256];
    sh_s[tid] = s;
    sh_q[tid] = q;
    __syncthreads();

    #pragma unroll
    for (int off = 128; off > 0; off >>= 1) {
        if (tid < off) {
            sh_s[tid] += sh_s[tid + off];
            sh_q[tid] += sh_q[tid + off];
        }
        __syncthreads();
    }

    if (tid == 0) {
        const double inv_n = 1.0 / (double)N_PER_C;
        double mean = sh_s[0] * inv_n;
        double var  = sh_q[0] * inv_n - mean * mean;
        double scale = (double)w[c] * rsqrt(var + 1e-5);
        g_scale[c] = (float)scale;
        g_shift[c] = (float)((double)bias[c] - mean * scale);
    }
}

// ---------------------------------------------------------------------------
// Kernel 2: stage the bucket table to global (tiny; 8 blocks).
// ---------------------------------------------------------------------------
__global__ void __launch_bounds__(256) stage_tab_kernel(const BucketTab tab)
{
    const int i = blockIdx.x * 256 + threadIdx.x;
    if (i < NB) g_tab[i] = tab.b[i];
}

// ---------------------------------------------------------------------------
// Kernel 3a (fast path): direct-mapped float2 bucket lookup, grid-stride.
// bucket = (edge, packed{v_hi in high 16 bits, v_lo in low 16} as bf16)
// value  = (a > edge) ? v_hi : v_lo ; result sign = sign(x).
// ---------------------------------------------------------------------------
__global__ void __launch_bounds__(256) lif_bucket_kernel(
    const float* __restrict__ act,
    float* __restrict__ out)
{
    __shared__ float2 sb[NB];
    for (int i = threadIdx.x; i < NB; i += 256)
        sb[i] = g_tab[i];                       // coalesced LDG
    __syncthreads();

    const int base = blockIdx.x * 256 + threadIdx.x;

    #pragma unroll
    for (int chunk = 0; chunk < LIF_CHUNKS; ++chunk) {
        const int i = base + chunk * (LIF_BLOCKS * 256);  // float4 index
        const int c = (i >> 7) & (C_DIM - 1);

        const float sc = g_scale[c];
        const float sh = g_shift[c];

        float4 v = ((const float4*)act)[i];
        float xs[4] = { fmaf(v.x, sc, sh), fmaf(v.y, sc, sh),
                        fmaf(v.z, sc, sh), fmaf(v.w, sc, sh) };
        float r[4];

        #pragma unroll
        for (int k = 0; k < 4; ++k) {
            const float a = fabsf(xs[k]);
            int idx = (int)(a * BSCALE);
            idx = min(idx, NB - 1);
            const float2 bk = sb[idx];
            const unsigned pv = __float_as_uint(bk.y);
            const unsigned sel = (a > bk.x) ? (pv & 0xFFFF0000u) : (pv << 16);
            r[k] = __uint_as_float(sel |
                      (__float_as_uint(xs[k]) & 0x80000000u));
        }

        ((float4*)out)[i] = make_float4(r[0], r[1], r[2], r[3]);
    }
}

// ---------------------------------------------------------------------------
// Kernel 3b (fallback, R5-verified 19.5us): 64-entry binary-search LUT.
// ---------------------------------------------------------------------------
__global__ void __launch_bounds__(256) lif_lut_kernel(
    const float* __restrict__ act,
    float* __restrict__ out,
    const LifTab tab)
{
    __shared__ float se[64];
    __shared__ float sv[64];
    if (threadIdx.x < 64) {
        se[threadIdx.x] = tab.e[threadIdx.x];
        sv[threadIdx.x] = tab.v[threadIdx.x];
    }
    __syncthreads();

    const int i = blockIdx.x * 256 + threadIdx.x;
    const int c = (i >> 7) & (C_DIM - 1);
    const float sc = g_scale[c];
    const float sh = g_shift[c];

    float4 v = ((const float4*)act)[i];
    float xs[4] = { fmaf(v.x, sc, sh), fmaf(v.y, sc, sh),
                    fmaf(v.z, sc, sh), fmaf(v.w, sc, sh) };
    float r[4];

    #pragma unroll
    for (int k = 0; k < 4; ++k) {
        const float a = fabsf(xs[k]);
        int pos = 0;
        #pragma unroll
        for (int s = 32; s > 0; s >>= 1)
            if (se[pos + s - 1] < a) pos += s;
        r[k] = __uint_as_float(__float_as_uint(sv[pos]) |
                               (__float_as_uint(xs[k]) & 0x80000000u));
    }

    ((float4*)out)[i] = make_float4(r[0], r[1], r[2], r[3]);
}

// ---------------------------------------------------------------------------
// Kernel 3c (last resort, R2-verified): direct 16-step scan.
// ---------------------------------------------------------------------------
__device__ __forceinline__ float lif16(float x)
{
    float mem = x;
    float sgn = __int_as_float((__float_as_int(mem) & 0x80000000) | 0x3f800000);
    float spk = (fabsf(mem) > 1.0f) ? sgn : 0.0f;
    float sum = spk;
    #pragma unroll
    for (int t = 1; t < 16; ++t) {
        mem = fmaf(0.9f, mem, x - spk);
        sgn = __int_as_float((__float_as_int(mem) & 0x80000000) | 0x3f800000);
        spk = (fabsf(mem) > 1.0f) ? sgn : 0.0f;
        sum += spk;
    }
    return sum * 0.0625f;
}

__global__ void __launch_bounds__(256) lif_kernel(
    const float* __restrict__ act,
    float* __restrict__ out)
{
    const int i = blockIdx.x * 256 + threadIdx.x;
    const int c = (i >> 7) & (C_DIM - 1);
    const float sc = g_scale[c];
    const float sh = g_shift[c];
    float4 v = ((const float4*)act)[i];
    float4 r;
    r.x = lif16(fmaf(v.x, sc, sh));
    r.y = lif16(fmaf(v.y, sc, sh));
    r.z = lif16(fmaf(v.z, sc, sh));
    r.w = lif16(fmaf(v.w, sc, sh));
    ((float4*)out)[i] = r;
}

// ===========================================================================
// Host-side machinery.
// ===========================================================================
static float host_lif16(float x)
{
    float mem = x;
    float spk = (fabsf(mem) > 1.0f) ? copysignf(1.0f, mem) : 0.0f;
    float sum = spk;
    for (int t = 1; t < 16; ++t) {
        mem = fmaf(0.9f, mem, x - spk);
        spk = (fabsf(mem) > 1.0f) ? copysignf(1.0f, mem) : 0.0f;
        sum += spk;
    }
    return sum * 0.0625f;
}

static inline unsigned f2u(float f) { unsigned u; std::memcpy(&u, &f, 4); return u; }
static inline float u2f(unsigned u) { float f; std::memcpy(&f, &u, 4); return f; }

static float host_bisect_edge(float lo, float hi, float vlo)
{
    for (int it = 0; it < 64; ++it) {
        unsigned a = f2u(lo), b = f2u(hi);
        if (b - a <= 1u) break;
        float m = u2f(a + (b - a) / 2u);
        if (host_lif16(m) == vlo) lo = m; else hi = m;
    }
    return lo;
}

// Enumerate edges/vals of the piecewise-constant f(|x|).
static int host_find_edges(float* edges, float* vals, int maxK)
{
    int K = 0;
    float cur = host_lif16(0.0f);
    float px = 0.0f;
    vals[0] = cur;
    bool overflow = false;

    auto feed = [&](float x) {
        float fv = host_lif16(x);
        if (fv != cur) {
            if (K < maxK) {
                edges[K] = host_bisect_edge(px, x, cur);
                ++K;
                vals[K] = fv;
            } else overflow = true;
            cur = fv;
        }
        px = x;
    };

    const int N1 = 1 << 20;
    for (int j = 1; j <= N1; ++j)
        feed(1.25f * ((float)j * (1.0f / (float)N1)));
    for (int j = 1; j <= 15104; ++j)
        feed(1.25f + (float)j * 0.0009765625f);

    return overflow ? -1 : K;
}

// Exact replica of device bucket index arithmetic (fp32 mul, truncate).
static inline int host_bidx(float a)
{
    float p = a * BSCALE;          // single-precision rn multiply
    int idx = (int)p;              // truncation == device F2I.rz
    return idx > NB - 1 ? NB - 1 : idx;
}

static float host_bucket_eval(const BucketTab& bt, float a)
{
    const float2& b = bt.b[host_bidx(a)];
    unsigned pv = f2u(b.y);
    unsigned sel = (a > b.x) ? (pv & 0xFFFF0000u) : (pv << 16);
    return u2f(sel);
}

// Build + validate bucket table (<=1 edge per bucket; bf16-exact values).
static bool host_build_buckets(BucketTab& bt,
                               const float* edges, const float* vals, int K)
{
    int i = 0;
    for (int j = 0; j < NB; ++j) {
        if (i < K && host_bidx(edges[i]) < j) return false;
        int i0 = i, cnt = 0;
        while (i < K && host_bidx(edges[i]) == j) { ++cnt; ++i; }
        if (cnt > 1) return false;

        float e = FLT_MAX;
        float vlo = vals[i0], vhi = vals[i0];
        if (cnt == 1) { e = edges[i0]; vhi = vals[i0 + 1]; }

        unsigned ulo = f2u(vlo), uhi = f2u(vhi);
        if ((ulo & 0xFFFFu) || (uhi & 0xFFFFu)) return false; // not bf16-exact
        float2 b;
        b.x = e;
        b.y = u2f((uhi & 0xFFFF0000u) | (ulo >> 16));
        bt.b[j] = b;
    }
    if (i != K) return false;

    auto chk = [&](float a) -> bool {
        float ref = host_lif16(a);
        return ref >= 0.0f && host_bucket_eval(bt, a) == ref;
    };
    // Strong checks: every edge +/-1 ulp, every bucket boundary +/-1 ulp.
    for (int k = 0; k < K; ++k) {
        float e = edges[k];
        if (!chk(e)) return false;
        if (!chk(u2f(f2u(e) + 1u))) return false;
        if (f2u(e) > 0 && !chk(u2f(f2u(e) - 1u))) return false;
    }
    for (int j = 1; j < NB; ++j) {
        float bnd = (float)j * (1.25f / (float)NB);
        if (!chk(bnd)) return false;
        if (!chk(u2f(f2u(bnd) + 1u))) return false;
        if (!chk(u2f(f2u(bnd) - 1u))) return false;
    }
    // Interior grid (2^18: ~600x finer than min inter-edge gap).
    const int NV = 1 << 18;
    for (int j = 0; j <= NV; ++j)
        if (!chk(1.25f * ((float)j * (1.0f / (float)NV)))) return false;
    for (int j = 1; j <= 2048; ++j)
        if (!chk(1.25f + (float)j * 0.0073242187f)) return false;
    return true;
}

static float host_lut_eval(const LifTab& tab, float a)
{
    int pos = 0;
    for (int s = 32; s > 0; s >>= 1)
        if (tab.e[pos + s - 1] < a) pos += s;
    return tab.v[pos];
}

static bool host_build_lut(LifTab& tab,
                           const float* edges, const float* vals, int K)
{
    if (K > 63) return false;
    for (int i2 = K; i2 < 64; ++i2) tab.e[i2] = FLT_MAX;
    for (int i2 = 0; i2 < K; ++i2)  tab.e[i2] = edges[i2];
    for (int i2 = 0; i2 <= K; ++i2) tab.v[i2] = vals[i2];
    for (int i2 = K + 1; i2 < 64; ++i2) tab.v[i2] = vals[K];

    for (int i2 = 0; i2 < K; ++i2) {
        float e = tab.e[i2];
        float eu = u2f(f2u(e) + 1u);
        if (host_lut_eval(tab, e)  != host_lif16(e))  return false;
        if (host_lut_eval(tab, eu) != host_lif16(eu)) return false;
    }
    for (int j = 0; j <= 4096; ++j) {
        float x = 1.25f * ((float)j / 4096.0f);
        if (host_lut_eval(tab, x) != host_lif16(x)) return false;
    }
    return true;
}

// ---------------------------------------------------------------------------
// Launch. Inputs (metadata order): activations, bn_weight, bn_bias.
// ---------------------------------------------------------------------------
extern "C" void kernel_launch(void* const* d_in, const int* in_sizes, int n_in,
                              void* d_out, int out_size)
{
    const float* act  = (const float*)d_in[0];
    const float* w    = (const float*)d_in[1];
    const float* bias = (const float*)d_in[2];
    float* out = (float*)d_out;

    static float edges[96], vals[97];
    int K = host_find_edges(edges, vals, 90);

    static BucketTab btab;                      // 16 KB; static: off stack
    bool bucket_ok = (K >= 0) && host_build_buckets(btab, edges, vals, K);
    LifTab ltab;
    bool lut_ok = (K >= 0) && host_build_lut(ltab, edges, vals, K);

    bn_stats_kernel<<<C_DIM, 256>>>(act, w, bias);

    if (bucket_ok) {
        stage_tab_kernel<<<NB / 256, 256>>>(btab);
        lif_bucket_kernel<<<LIF_BLOCKS, 256>>>(act, out);
    } else if (lut_ok) {
        lif_lut_kernel<<<TOTAL_F4 / 256, 256>>>(act, out, ltab);
    } else {
        lif_kernel<<<TOTAL_F4 / 256, 256>>>(act, out);
    }
}